// round 1
// baseline (speedup 1.0000x reference)
#include <cuda_runtime.h>
#include <cuda_bf16.h>
#include <cstdint>

// GNNIntraAgg: out[b, :] = relu( mean_k features[neigh_ids[b,k], :] )
// B=16384, K=32, N=100000, D=256, fp32.
//
// Strategy: table (102 MB) fits in L2 -> gather traffic is L2-hit bound.
// Block = 256 threads = 4 batch rows x 64 threads; each thread owns one
// float4 column slice, fully coalesced 1024B row reads, K-loop unrolled
// for MLP to hide L2 latency.

namespace {
constexpr int K = 32;
constexpr int D = 256;
constexpr int DV = D / 4;              // float4 columns = 64
constexpr int ROWS_PER_BLOCK = 4;
constexpr int THREADS = ROWS_PER_BLOCK * DV;  // 256
}

__global__ __launch_bounds__(THREADS)
void gnn_agg_kernel(const int* __restrict__ neigh_ids,
                    const float4* __restrict__ features,
                    float4* __restrict__ out,
                    int B)
{
    __shared__ int sid[ROWS_PER_BLOCK][K];

    const int row0 = blockIdx.x * ROWS_PER_BLOCK;
    const int tid  = threadIdx.x;

    // Stage the 4*32 neighbor ids through shared memory (coalesced LDG).
    {
        int i = tid;
        if (i < ROWS_PER_BLOCK * K) {
            int r = i / K;
            int k = i % K;
            int b = row0 + r;
            sid[r][k] = (b < B) ? neigh_ids[(size_t)b * K + k] : 0;
        }
    }
    __syncthreads();

    const int r = tid / DV;            // local batch row 0..3
    const int c = tid % DV;            // float4 column 0..63
    const int b = row0 + r;
    if (b >= B) return;

    float4 acc = make_float4(0.f, 0.f, 0.f, 0.f);

#pragma unroll
    for (int k = 0; k < K; ++k) {
        const size_t off = (size_t)sid[r][k] * DV + c;
        const float4 v = __ldg(&features[off]);
        acc.x += v.x;
        acc.y += v.y;
        acc.z += v.z;
        acc.w += v.w;
    }

    const float s = 1.0f / (float)K;
    acc.x = fmaxf(acc.x * s, 0.f);
    acc.y = fmaxf(acc.y * s, 0.f);
    acc.z = fmaxf(acc.z * s, 0.f);
    acc.w = fmaxf(acc.w * s, 0.f);

    out[(size_t)b * DV + c] = acc;
}

extern "C" void kernel_launch(void* const* d_in, const int* in_sizes, int n_in,
                              void* d_out, int out_size)
{
    const int* neigh_ids    = (const int*)d_in[0];      // [B, K] int32
    const float4* features  = (const float4*)d_in[1];   // [N, D] fp32 as float4
    float4* out             = (float4*)d_out;           // [B, D] fp32 as float4

    const int B = in_sizes[0] / K;                      // 16384

    const int grid = (B + ROWS_PER_BLOCK - 1) / ROWS_PER_BLOCK;
    gnn_agg_kernel<<<grid, THREADS>>>(neigh_ids, features, out, B);
}